// round 3
// baseline (speedup 1.0000x reference)
#include <cuda_runtime.h>
#include <cstdint>

#define H 1024
#define SEQ 512
#define VOCAB 50257
#define NB 148
#define NT 256
#define NWARP (NB * 8)

// output layout: [log_softmax(VOCAB) | h(H) | c(H) | attn_weights(SEQ)]
#define OUT_H  (VOCAB)
#define OUT_C  (VOCAB + H)
#define OUT_AW (VOCAB + 2 * H)

// ---------------- device scratch (no allocations allowed) ----------------
__device__ float g_attn_logits[SEQ];
__device__ float g_attn_applied[H];
__device__ float g_x[H];
__device__ float g_h[H];
__device__ float g_pmax[NB];
__device__ float g_psum[NB];
__device__ unsigned g_barcnt;   // monotonic grid-barrier counter (replay-safe)

__device__ __forceinline__ float dot4(float4 a, float4 b) {
    return a.x * b.x + a.y * b.y + a.z * b.z + a.w * b.w;
}

__device__ __forceinline__ float warp_sum(float v) {
#pragma unroll
    for (int o = 16; o > 0; o >>= 1) v += __shfl_down_sync(0xffffffffu, v, o);
    return v;
}

__device__ __forceinline__ float sigmoidf_(float x) {
    return 1.0f / (1.0f + expf(-x));
}

// Grid-wide barrier: monotonic counter, sense encoded in target multiple.
// Safe across graph replays (no reset needed). All 148 blocks are resident
// in wave 1 (grid <= #SMs), so spinning cannot deadlock.
__device__ __forceinline__ void grid_sync() {
    __syncthreads();
    if (threadIdx.x == 0) {
        __threadfence();                                   // release
        unsigned old = atomicAdd(&g_barcnt, 1u);
        unsigned target = (old / NB + 1u) * NB;
        while (*((volatile unsigned*)&g_barcnt) < target) { }
        __threadfence();                                   // acquire
    }
    __syncthreads();
}

__global__ void __launch_bounds__(NT) mega_kernel(
    const int* __restrict__ idx,
    const float* __restrict__ h0,
    const float* __restrict__ c0,
    const float* __restrict__ enc,
    const float* __restrict__ emb,
    const float* __restrict__ attn_W,
    const float* __restrict__ attn_b,
    const float* __restrict__ comb_W,
    const float* __restrict__ comb_b,
    const float* __restrict__ w_ih,
    const float* __restrict__ w_hh,
    const float* __restrict__ b_ih,
    const float* __restrict__ b_hh,
    const float* __restrict__ out_W,
    const float* __restrict__ out_b,
    float* __restrict__ out)
{
    __shared__ float4 sh4[512];     // 8KB staged input vector (2048 floats)
    __shared__ float  s_aw[SEQ];    // attention weights (block-local copy)
    __shared__ float  s_red[NT];
    __shared__ float  s_m[8], s_s[8];

    const int tid  = threadIdx.x;
    const int warp = tid >> 5;
    const int lane = tid & 31;
    const int gw   = blockIdx.x * 8 + warp;   // global warp id 0..1183

    const int row = idx[0];
    const float4* e4  = (const float4*)(emb + (size_t)row * H);
    const float4* h04 = (const float4*)h0;

    // ================= phase 1: attention scores (warp per row) =================
    if (gw < SEQ) {
        const float4* w = (const float4*)(attn_W + (size_t)gw * (2 * H));
        float acc = 0.0f;
#pragma unroll
        for (int k = 0; k < 8; k++) { int i = lane + 32 * k; acc += dot4(e4[i],  w[i]); }
#pragma unroll
        for (int k = 0; k < 8; k++) { int i = lane + 32 * k; acc += dot4(h04[i], w[256 + i]); }
        acc = warp_sum(acc);
        if (lane == 0) g_attn_logits[gw] = acc + attn_b[gw];
    }
    if (blockIdx.x == NB - 1) {     // this block's warps are idle in phase 1
        for (int i = tid; i < H; i += NT) g_attn_applied[i] = 0.0f;
    }
    grid_sync();

    // ================= phase 2: softmax (redundant per block, reads L2) =========
    {
        float v0 = g_attn_logits[tid];
        float v1 = g_attn_logits[tid + 256];
        s_red[tid] = fmaxf(v0, v1);
        __syncthreads();
        for (int k = 128; k > 0; k >>= 1) {
            if (tid < k) s_red[tid] = fmaxf(s_red[tid], s_red[tid + k]);
            __syncthreads();
        }
        float m = s_red[0];
        __syncthreads();
        float e0 = expf(v0 - m), e1 = expf(v1 - m);
        s_red[tid] = e0 + e1;
        __syncthreads();
        for (int k = 128; k > 0; k >>= 1) {
            if (tid < k) s_red[tid] += s_red[tid + k];
            __syncthreads();
        }
        float inv = 1.0f / s_red[0];
        float w0 = e0 * inv, w1 = e1 * inv;
        s_aw[tid] = w0;
        s_aw[tid + 256] = w1;
        if (blockIdx.x == 0) {
            out[OUT_AW + tid] = w0;
            out[OUT_AW + tid + 256] = w1;
        }
        __syncthreads();
    }

    // ================= phase 3: attn_applied (128 blocks x 4 rows, atomics) ======
    if (blockIdx.x < 128) {
        int r0 = blockIdx.x * 4;
        const float4* enc4 = (const float4*)enc;
        float4 acc = make_float4(0.f, 0.f, 0.f, 0.f);
#pragma unroll
        for (int s = 0; s < 4; s++) {
            float w = s_aw[r0 + s];
            float4 v = enc4[(size_t)(r0 + s) * 256 + tid];
            acc.x += w * v.x; acc.y += w * v.y; acc.z += w * v.z; acc.w += w * v.w;
        }
        atomicAdd(&g_attn_applied[4 * tid + 0], acc.x);
        atomicAdd(&g_attn_applied[4 * tid + 1], acc.y);
        atomicAdd(&g_attn_applied[4 * tid + 2], acc.z);
        atomicAdd(&g_attn_applied[4 * tid + 3], acc.w);
    }
    grid_sync();

    // ================= phase 4: x = relu([emb, attn_applied] @ comb_W.T + b) =====
    sh4[tid]       = e4[tid];
    sh4[256 + tid] = ((const float4*)g_attn_applied)[tid];
    __syncthreads();
    if (gw < H) {
        const float4* w = (const float4*)(comb_W + (size_t)gw * (2 * H));
        float acc = 0.0f;
#pragma unroll
        for (int k = 0; k < 16; k++) { int i = lane + 32 * k; acc += dot4(sh4[i], w[i]); }
        acc = warp_sum(acc);
        if (lane == 0) g_x[gw] = fmaxf(acc + comb_b[gw], 0.0f);
    }
    grid_sync();

    // ================= phase 5: LSTM gates + elementwise (warp per j) ============
    sh4[tid]       = ((const float4*)g_x)[tid];
    sh4[256 + tid] = h04[tid];
    __syncthreads();
    if (gw < H) {
        const int j = gw;
        float gt[4];
#pragma unroll
        for (int g = 0; g < 4; g++) {
            size_t r = (size_t)g * H + j;
            const float4* wi = (const float4*)(w_ih + r * H);
            const float4* wh = (const float4*)(w_hh + r * H);
            float acc = 0.0f;
#pragma unroll
            for (int k = 0; k < 8; k++) {
                int i = lane + 32 * k;
                acc += dot4(sh4[i], wi[i]);
                acc += dot4(sh4[256 + i], wh[i]);
            }
            acc = warp_sum(acc);
            gt[g] = acc + b_ih[r] + b_hh[r];    // valid on lane 0
        }
        if (lane == 0) {
            float i_  = sigmoidf_(gt[0]);
            float f_  = sigmoidf_(gt[1]);
            float gch = tanhf(gt[2]);
            float o_  = sigmoidf_(gt[3]);
            float c = f_ * c0[j] + i_ * gch;
            float h = o_ * tanhf(c);
            g_h[j] = h;
            out[OUT_H + j] = h;
            out[OUT_C + j] = c;
        }
    }
    grid_sync();

    // ================= phase 6: logits + block-local online LSE ==================
    sh4[tid] = ((const float4*)g_h)[tid];
    __syncthreads();
    float lm = -1e30f, ls = 0.0f;
    for (int r = gw; r < VOCAB; r += NWARP) {
        const float4* w = (const float4*)(out_W + (size_t)r * H);
        float acc = 0.0f;
#pragma unroll
        for (int k = 0; k < 8; k++) { int i = lane + 32 * k; acc += dot4(sh4[i], w[i]); }
        acc = warp_sum(acc);
        if (lane == 0) {
            float L = acc + out_b[r];
            out[r] = L;
            if (L > lm) { ls = ls * expf(lm - L) + 1.0f; lm = L; }
            else        { ls += expf(L - lm); }
        }
    }
    if (lane == 0) { s_m[warp] = lm; s_s[warp] = ls; }
    __syncthreads();
    if (tid == 0) {
        float m = s_m[0], s = s_s[0];
#pragma unroll
        for (int w2 = 1; w2 < 8; w2++) {
            float m2 = s_m[w2], s2 = s_s[w2];
            float M = fmaxf(m, m2);
            s = s * expf(m - M) + s2 * expf(m2 - M);
            m = M;
        }
        g_pmax[blockIdx.x] = m;
        g_psum[blockIdx.x] = s;
    }
    grid_sync();

    // ================= phase 7+8: final LSE (redundant per block) + subtract =====
    {
        float* rm = (float*)sh4;       // reuse: 256 floats
        float* rs = rm + 256;          // 256 floats
        rm[tid] = (tid < NB) ? g_pmax[tid] : -1e30f;
        rs[tid] = (tid < NB) ? g_psum[tid] : 0.0f;
        __syncthreads();
        for (int k = 128; k > 0; k >>= 1) {
            if (tid < k) {
                float m2 = rm[tid + k], s2 = rs[tid + k];
                float M = fmaxf(rm[tid], m2);
                rs[tid] = rs[tid] * expf(rm[tid] - M) + s2 * expf(m2 - M);
                rm[tid] = M;
            }
            __syncthreads();
        }
        float lse = rm[0] + logf(rs[0]);
        int base = blockIdx.x * 340;                 // 340 * 148 >= VOCAB
        int lim = min(base + 340, VOCAB);
        for (int i = base + tid; i < lim; i += NT) out[i] -= lse;
    }
}

extern "C" void kernel_launch(void* const* d_in, const int* in_sizes, int n_in,
                              void* d_out, int out_size) {
    const int*   idx     = (const int*)  d_in[0];
    const float* h0      = (const float*)d_in[1];
    const float* c0      = (const float*)d_in[2];
    const float* enc     = (const float*)d_in[3];
    const float* emb     = (const float*)d_in[4];
    const float* attn_W  = (const float*)d_in[5];
    const float* attn_b  = (const float*)d_in[6];
    const float* comb_W  = (const float*)d_in[7];
    const float* comb_b  = (const float*)d_in[8];
    const float* w_ih    = (const float*)d_in[9];
    const float* w_hh    = (const float*)d_in[10];
    const float* b_ih    = (const float*)d_in[11];
    const float* b_hh    = (const float*)d_in[12];
    const float* out_W   = (const float*)d_in[13];
    const float* out_b   = (const float*)d_in[14];
    float* out = (float*)d_out;

    mega_kernel<<<NB, NT>>>(idx, h0, c0, enc, emb, attn_W, attn_b,
                            comb_W, comb_b, w_ih, w_hh, b_ih, b_hh,
                            out_W, out_b, out);
}

// round 4
// speedup vs baseline: 1.3190x; 1.3190x over previous
#include <cuda_runtime.h>
#include <cstdint>

#define H 1024
#define SEQ 512
#define VOCAB 50257

// logits kernel: 8 warps/block, 2 rows/warp -> 16 rows/block
#define LROWS 16
#define NLOGB ((VOCAB + LROWS - 1) / LROWS)   // 3142

// output layout: [log_softmax(VOCAB) | h(H) | c(H) | attn_weights(SEQ)]
#define OUT_H  (VOCAB)
#define OUT_C  (VOCAB + H)
#define OUT_AW (VOCAB + 2 * H)

// ---------------- device scratch ----------------
__device__ float g_attn_logits[SEQ];
__device__ float g_attn_w[SEQ];
__device__ float g_attn_applied[H];
__device__ float g_x[H];
__device__ float g_h[H];
__device__ float g_pmax[NLOGB];
__device__ float g_psum[NLOGB];

__device__ __forceinline__ float dot4(float4 a, float4 b) {
    return a.x * b.x + a.y * b.y + a.z * b.z + a.w * b.w;
}

__device__ __forceinline__ float warp_sum(float v) {
#pragma unroll
    for (int o = 16; o > 0; o >>= 1) v += __shfl_down_sync(0xffffffffu, v, o);
    return v;
}

__device__ __forceinline__ float sigmoidf_(float x) {
    return 1.0f / (1.0f + expf(-x));
}

// ---- 1. attention scores: warp per row, explicit prefetch ----
__global__ void __launch_bounds__(256) attn_score_kernel(
        const int* __restrict__ idx, const float* __restrict__ emb,
        const float* __restrict__ h0, const float* __restrict__ attn_W,
        const float* __restrict__ attn_b) {
    __shared__ float4 sin[512];               // [emb_row | h0]
    int t = threadIdx.x, warp = t >> 5, lane = t & 31;
    int row = idx[0];
    sin[t]       = ((const float4*)(emb + (size_t)row * H))[t];
    sin[256 + t] = ((const float4*)h0)[t];
    __syncthreads();
    int r = blockIdx.x * 8 + warp;            // grid = 64
    const float4* w = (const float4*)(attn_W + (size_t)r * (2 * H));
    float4 wr[16];
#pragma unroll
    for (int k = 0; k < 16; k++) wr[k] = __ldcs(&w[lane + 32 * k]);
    float acc = 0.0f;
#pragma unroll
    for (int k = 0; k < 16; k++) acc += dot4(sin[lane + 32 * k], wr[k]);
    acc = warp_sum(acc);
    if (lane == 0) g_attn_logits[r] = acc + attn_b[r];
}

// ---- 2. softmax over SEQ + zero attn_applied accumulator ----
__global__ void softmax_kernel(float* __restrict__ out) {
    __shared__ float sdata[SEQ];
    int t = threadIdx.x;                      // 512 threads
    g_attn_applied[t] = 0.0f;
    g_attn_applied[t + 512] = 0.0f;
    float v = g_attn_logits[t];
    sdata[t] = v;
    __syncthreads();
    for (int s = SEQ >> 1; s > 0; s >>= 1) {
        if (t < s) sdata[t] = fmaxf(sdata[t], sdata[t + s]);
        __syncthreads();
    }
    float m = sdata[0];
    __syncthreads();
    float e = expf(v - m);
    sdata[t] = e;
    __syncthreads();
    for (int s = SEQ >> 1; s > 0; s >>= 1) {
        if (t < s) sdata[t] += sdata[t + s];
        __syncthreads();
    }
    float w = e / sdata[0];
    g_attn_w[t] = w;
    out[OUT_AW + t] = w;
}

// ---- 3. attn_applied = attn_w @ encoder_outputs (32 blocks x 16 rows) ----
__global__ void attn_applied_kernel(const float* __restrict__ enc) {
    int t = threadIdx.x;                      // 256 threads
    int r0 = blockIdx.x * 16;                 // 32 blocks
    const float4* e4 = (const float4*)enc;
    float4 acc = make_float4(0.f, 0.f, 0.f, 0.f);
#pragma unroll
    for (int s = 0; s < 16; s++) {
        float w = g_attn_w[r0 + s];
        float4 v = e4[(size_t)(r0 + s) * 256 + t];
        acc.x += w * v.x; acc.y += w * v.y; acc.z += w * v.z; acc.w += w * v.w;
    }
    atomicAdd(&g_attn_applied[4 * t + 0], acc.x);
    atomicAdd(&g_attn_applied[4 * t + 1], acc.y);
    atomicAdd(&g_attn_applied[4 * t + 2], acc.z);
    atomicAdd(&g_attn_applied[4 * t + 3], acc.w);
}

// ---- 4. x = relu([emb, attn_applied] @ comb_W.T + b): warp/row, prefetch ----
__global__ void __launch_bounds__(256) comb_kernel(
        const int* __restrict__ idx, const float* __restrict__ emb,
        const float* __restrict__ comb_W, const float* __restrict__ comb_b) {
    __shared__ float4 sin[512];
    int t = threadIdx.x, warp = t >> 5, lane = t & 31;
    int row = idx[0];
    sin[t]       = ((const float4*)(emb + (size_t)row * H))[t];
    sin[256 + t] = ((const float4*)g_attn_applied)[t];
    __syncthreads();
    int r = blockIdx.x * 8 + warp;            // grid = 128
    const float4* w = (const float4*)(comb_W + (size_t)r * (2 * H));
    float4 wr[16];
#pragma unroll
    for (int k = 0; k < 16; k++) wr[k] = __ldcs(&w[lane + 32 * k]);
    float acc = 0.0f;
#pragma unroll
    for (int k = 0; k < 16; k++) acc += dot4(sin[lane + 32 * k], wr[k]);
    acc = warp_sum(acc);
    if (lane == 0) g_x[r] = fmaxf(acc + comb_b[r], 0.0f);
}

// ---- 5. gates + LSTM fused: block j, warp per gate, prefetch ----
__global__ void __launch_bounds__(128) gates_lstm_kernel(
        const float* __restrict__ h0, const float* __restrict__ c0,
        const float* __restrict__ w_ih, const float* __restrict__ w_hh,
        const float* __restrict__ b_ih, const float* __restrict__ b_hh,
        float* __restrict__ out) {
    __shared__ float4 sx[256], sh0[256];
    __shared__ float sgate[4];
    int t = threadIdx.x, warp = t >> 5, lane = t & 31;
    sx[t]        = ((const float4*)g_x)[t];
    sx[128 + t]  = ((const float4*)g_x)[128 + t];
    sh0[t]       = ((const float4*)h0)[t];
    sh0[128 + t] = ((const float4*)h0)[128 + t];
    __syncthreads();
    int j = blockIdx.x;                       // grid = H
    size_t r = (size_t)warp * H + j;
    const float4* wi = (const float4*)(w_ih + r * H);
    const float4* wh = (const float4*)(w_hh + r * H);
    float4 wir[8], whr[8];
#pragma unroll
    for (int k = 0; k < 8; k++) { int i = lane + 32 * k; wir[k] = __ldcs(&wi[i]); whr[k] = __ldcs(&wh[i]); }
    float acc = 0.0f;
#pragma unroll
    for (int k = 0; k < 8; k++) {
        int i = lane + 32 * k;
        acc += dot4(sx[i], wir[k]);
        acc += dot4(sh0[i], whr[k]);
    }
    acc = warp_sum(acc);
    if (lane == 0) sgate[warp] = acc + b_ih[r] + b_hh[r];
    __syncthreads();
    if (t == 0) {
        float i_ = sigmoidf_(sgate[0]);
        float f_ = sigmoidf_(sgate[1]);
        float g_ = tanhf(sgate[2]);
        float o_ = sigmoidf_(sgate[3]);
        float c = f_ * c0[j] + i_ * g_;
        float h = o_ * tanhf(c);
        g_h[j] = h;
        out[OUT_H + j] = h;
        out[OUT_C + j] = c;
    }
}

// ---- 6. logits + fused block LSE: 2 rows per warp ----
__global__ void __launch_bounds__(256) logits_kernel(
        const float* __restrict__ out_W, const float* __restrict__ out_b,
        float* __restrict__ out) {
    __shared__ float4 sh[256];
    __shared__ float s_m[8], s_s[8];
    int t = threadIdx.x, warp = t >> 5, lane = t & 31;
    sh[t] = ((const float4*)g_h)[t];
    __syncthreads();
    int r0 = blockIdx.x * LROWS + warp * 2;   // grid = NLOGB
    int r1 = r0 + 1;
    float m = -1e30f, s = 0.0f;
    if (r0 < VOCAB) {
        const float4* w0 = (const float4*)(out_W + (size_t)r0 * H);
        const float4* w1 = (const float4*)(out_W + (size_t)r1 * H);
        bool has1 = (r1 < VOCAB);
        float acc0 = 0.0f, acc1 = 0.0f;
#pragma unroll
        for (int k = 0; k < 8; k++) {
            int i = lane + 32 * k;
            float4 hv = sh[i];
            acc0 += dot4(hv, __ldcs(&w0[i]));
            if (has1) acc1 += dot4(hv, __ldcs(&w1[i]));
        }
        acc0 = warp_sum(acc0);
        acc1 = warp_sum(acc1);
        if (lane == 0) {
            float L0 = acc0 + out_b[r0];
            out[r0] = L0;
            m = L0; s = 1.0f;
            if (has1) {
                float L1 = acc1 + out_b[r1];
                out[r1] = L1;
                float M = fmaxf(m, L1);
                s = expf(m - M) + expf(L1 - M);
                m = M;
            }
        }
    }
    if (lane == 0) { s_m[warp] = m; s_s[warp] = s; }
    __syncthreads();
    if (t == 0) {
        float M = s_m[0], S = s_s[0];
#pragma unroll
        for (int k = 1; k < 8; k++) {
            float m2 = s_m[k], s2 = s_s[k];
            float Mx = fmaxf(M, m2);
            S = S * expf(M - Mx) + s2 * expf(m2 - Mx);
            M = Mx;
        }
        g_pmax[blockIdx.x] = M;
        g_psum[blockIdx.x] = S;
    }
}

// ---- 7. final LSE combine (redundant per block) + subtract ----
__global__ void __launch_bounds__(256) sub_lse_kernel(float* __restrict__ out) {
    __shared__ float rm[256], rs[256];
    int t = threadIdx.x;
    float m = -1e30f, s = 0.0f;
    for (int i = t; i < NLOGB; i += 256) {
        float m2 = g_pmax[i], s2 = g_psum[i];
        float M = fmaxf(m, m2);
        s = s * expf(m - M) + s2 * expf(m2 - M);
        m = M;
    }
    rm[t] = m; rs[t] = s;
    __syncthreads();
    for (int k = 128; k > 0; k >>= 1) {
        if (t < k) {
            float m2 = rm[t + k], s2 = rs[t + k];
            float M = fmaxf(rm[t], m2);
            rs[t] = rs[t] * expf(rm[t] - M) + s2 * expf(m2 - M);
            rm[t] = M;
        }
        __syncthreads();
    }
    float lse = rm[0] + logf(rs[0]);
    int base = blockIdx.x * 1024;             // grid = 50
#pragma unroll
    for (int k = 0; k < 4; k++) {
        int i = base + t + 256 * k;
        if (i < VOCAB) out[i] -= lse;
    }
}

extern "C" void kernel_launch(void* const* d_in, const int* in_sizes, int n_in,
                              void* d_out, int out_size) {
    const int*   idx     = (const int*)  d_in[0];
    const float* h0      = (const float*)d_in[1];
    const float* c0      = (const float*)d_in[2];
    const float* enc     = (const float*)d_in[3];
    const float* emb     = (const float*)d_in[4];
    const float* attn_W  = (const float*)d_in[5];
    const float* attn_b  = (const float*)d_in[6];
    const float* comb_W  = (const float*)d_in[7];
    const float* comb_b  = (const float*)d_in[8];
    const float* w_ih    = (const float*)d_in[9];
    const float* w_hh    = (const float*)d_in[10];
    const float* b_ih    = (const float*)d_in[11];
    const float* b_hh    = (const float*)d_in[12];
    const float* out_W   = (const float*)d_in[13];
    const float* out_b   = (const float*)d_in[14];
    float* out = (float*)d_out;

    attn_score_kernel<<<SEQ / 8, 256>>>(idx, emb, h0, attn_W, attn_b);
    softmax_kernel<<<1, SEQ>>>(out);
    attn_applied_kernel<<<32, 256>>>(enc);
    comb_kernel<<<H / 8, 256>>>(idx, emb, comb_W, comb_b);
    gates_lstm_kernel<<<H, 128>>>(h0, c0, w_ih, w_hh, b_ih, b_hh, out);
    logits_kernel<<<NLOGB, 256>>>(out_W, out_b, out);
    sub_lse_kernel<<<(VOCAB + 1023) / 1024, 256>>>(out);
}